// round 13
// baseline (speedup 1.0000x reference)
#include <cuda_runtime.h>

// GLRFast forward: out[b,g,c,h,w] = patchs - sum_e ew[b,g,e,h,w] * nbr_e(patchs)
// nbr order (DELTAS): e0=(-1,0) up, e1=(0,-1) left, e2=(0,1) right, e3=(1,0) down
// Replicate ('edge') padding on H and W borders.
// Shapes: B=4, G=8, C=32, H=128, W=128 (fp32). node_degree (d_in[2]) unused.
//
// R11: flat block = 4 channels, NO channel loop. 16 back-to-back LDG.128
// (4 ew + 12 patchs) front-batched per thread -> MLP_p1 = 16. 4096 small
// blocks give ~7 waves (small tail) and rapid block turnover keeps the LSU
// fed. __stcs on the output stream (evict-first) so 67MB of dirty output
// doesn't evict read lines from the 126MB L2.

#define H_DIM 128
#define W_DIM 128
#define C_DIM 32
#define ROWS_PER_BLOCK 8
#define C_PER_BLOCK 4

__global__ __launch_bounds__(256) void glrfast_kernel(
    const float* __restrict__ patchs,
    const float* __restrict__ ew,
    float* __restrict__ out)
{
    const int lane = threadIdx.x;                         // 0..31 -> one full row per warp
    const int h    = blockIdx.x * ROWS_PER_BLOCK + threadIdx.y;
    const int c0   = blockIdx.y * C_PER_BLOCK;
    const int bg   = blockIdx.z;                          // 0..31 (= b*G + g)
    const int w0   = lane * 4;

    const int HW = H_DIM * W_DIM;

    const int hu = (h > 0)         ? h - 1 : 0;           // replicate pad
    const int hd = (h < H_DIM - 1) ? h + 1 : H_DIM - 1;

    const long off_c = (long)h  * W_DIM + w0;
    const long off_u = (long)hu * W_DIM + w0;
    const long off_d = (long)hd * W_DIM + w0;

    const float* pb = patchs + ((long)bg * C_DIM + c0) * HW;
    float*       ob = out    + ((long)bg * C_DIM + c0) * HW;

    // ---- front-batch ALL loads: 4 ew + 12 patchs LDG.128, no consumers between ----
    const float* ewb = ew + ((long)bg * 4) * HW + (long)h * W_DIM + w0;
    const float4 eN = *(const float4*)(ewb + 0L * HW);
    const float4 eW = *(const float4*)(ewb + 1L * HW);
    const float4 eE = *(const float4*)(ewb + 2L * HW);
    const float4 eS = *(const float4*)(ewb + 3L * HW);

    float4 cen[C_PER_BLOCK], up[C_PER_BLOCK], dn[C_PER_BLOCK];
#pragma unroll
    for (int cc = 0; cc < C_PER_BLOCK; ++cc) {
        const float* pc = pb + (long)cc * HW;
        cen[cc] = *(const float4*)(pc + off_c);
        up[cc]  = *(const float4*)(pc + off_u);
        dn[cc]  = *(const float4*)(pc + off_d);
    }

    // ---- w-direction neighbors via in-warp shuffles (warp == one row) ----
    float xm1[C_PER_BLOCK], xp4[C_PER_BLOCK];
#pragma unroll
    for (int cc = 0; cc < C_PER_BLOCK; ++cc) {
        xm1[cc] = __shfl_up_sync(0xffffffffu, cen[cc].w, 1);   // x[w0-1]
        xp4[cc] = __shfl_down_sync(0xffffffffu, cen[cc].x, 1); // x[w0+4]
    }
    if (lane == 0) {
#pragma unroll
        for (int cc = 0; cc < C_PER_BLOCK; ++cc) xm1[cc] = cen[cc].x;   // replicate x[0]
    }
    if (lane == 31) {
#pragma unroll
        for (int cc = 0; cc < C_PER_BLOCK; ++cc) xp4[cc] = cen[cc].w;   // replicate x[127]
    }

    // ---- compute + streaming stores ----
#pragma unroll
    for (int cc = 0; cc < C_PER_BLOCK; ++cc) {
        float4 o;
        o.x = cen[cc].x - (eN.x * up[cc].x + eW.x * xm1[cc]   + eE.x * cen[cc].y + eS.x * dn[cc].x);
        o.y = cen[cc].y - (eN.y * up[cc].y + eW.y * cen[cc].x + eE.y * cen[cc].z + eS.y * dn[cc].y);
        o.z = cen[cc].z - (eN.z * up[cc].z + eW.z * cen[cc].y + eE.z * cen[cc].w + eS.z * dn[cc].z);
        o.w = cen[cc].w - (eN.w * up[cc].w + eW.w * cen[cc].z + eE.w * xp4[cc]   + eS.w * dn[cc].w);
        __stcs((float4*)(ob + (long)cc * HW + off_c), o);
    }
}

extern "C" void kernel_launch(void* const* d_in, const int* in_sizes, int n_in,
                              void* d_out, int out_size)
{
    const float* patchs = (const float*)d_in[0];   // [4,8,32,128,128]
    const float* ew     = (const float*)d_in[1];   // [4,8,4,128,128]
    // d_in[2] = node_degree: unused in forward
    float* out = (float*)d_out;                    // [4,8,32,128,128]

    dim3 block(32, ROWS_PER_BLOCK);                           // 256 threads
    dim3 grid(H_DIM / ROWS_PER_BLOCK,                         // 16 h-tiles
              C_DIM / C_PER_BLOCK,                            // 8 c-chunks
              32);                                            // B*G planes

    glrfast_kernel<<<grid, block>>>(patchs, ew, out);
}

// round 14
// speedup vs baseline: 1.0408x; 1.0408x over previous
#include <cuda_runtime.h>

// GLRFast forward: out[b,g,c,h,w] = patchs - sum_e ew[b,g,e,h,w] * nbr_e(patchs)
// nbr order (DELTAS): e0=(-1,0) up, e1=(0,-1) left, e2=(0,1) right, e3=(1,0) down
// Replicate ('edge') padding on H and W borders.
// Shapes: B=4, G=8, C=32, H=128, W=128 (fp32). node_degree (d_in[2]) unused.
//
// R11: flat block = 4 channels, NO channel loop. 16 back-to-back LDG.128
// (4 ew + 12 patchs) front-batched per thread -> MLP_p1 = 16. 4096 small
// blocks give ~7 waves (small tail) and rapid block turnover keeps the LSU
// fed. __stcs on the output stream (evict-first) so 67MB of dirty output
// doesn't evict read lines from the 126MB L2.

#define H_DIM 128
#define W_DIM 128
#define C_DIM 32
#define ROWS_PER_BLOCK 8
#define C_PER_BLOCK 4

__global__ __launch_bounds__(256) void glrfast_kernel(
    const float* __restrict__ patchs,
    const float* __restrict__ ew,
    float* __restrict__ out)
{
    const int lane = threadIdx.x;                         // 0..31 -> one full row per warp
    const int h    = blockIdx.x * ROWS_PER_BLOCK + threadIdx.y;
    const int c0   = blockIdx.y * C_PER_BLOCK;
    const int bg   = blockIdx.z;                          // 0..31 (= b*G + g)
    const int w0   = lane * 4;

    const int HW = H_DIM * W_DIM;

    const int hu = (h > 0)         ? h - 1 : 0;           // replicate pad
    const int hd = (h < H_DIM - 1) ? h + 1 : H_DIM - 1;

    const long off_c = (long)h  * W_DIM + w0;
    const long off_u = (long)hu * W_DIM + w0;
    const long off_d = (long)hd * W_DIM + w0;

    const float* pb = patchs + ((long)bg * C_DIM + c0) * HW;
    float*       ob = out    + ((long)bg * C_DIM + c0) * HW;

    // ---- front-batch ALL loads: 4 ew + 12 patchs LDG.128, no consumers between ----
    const float* ewb = ew + ((long)bg * 4) * HW + (long)h * W_DIM + w0;
    const float4 eN = *(const float4*)(ewb + 0L * HW);
    const float4 eW = *(const float4*)(ewb + 1L * HW);
    const float4 eE = *(const float4*)(ewb + 2L * HW);
    const float4 eS = *(const float4*)(ewb + 3L * HW);

    float4 cen[C_PER_BLOCK], up[C_PER_BLOCK], dn[C_PER_BLOCK];
#pragma unroll
    for (int cc = 0; cc < C_PER_BLOCK; ++cc) {
        const float* pc = pb + (long)cc * HW;
        cen[cc] = *(const float4*)(pc + off_c);
        up[cc]  = *(const float4*)(pc + off_u);
        dn[cc]  = *(const float4*)(pc + off_d);
    }

    // ---- w-direction neighbors via in-warp shuffles (warp == one row) ----
    float xm1[C_PER_BLOCK], xp4[C_PER_BLOCK];
#pragma unroll
    for (int cc = 0; cc < C_PER_BLOCK; ++cc) {
        xm1[cc] = __shfl_up_sync(0xffffffffu, cen[cc].w, 1);   // x[w0-1]
        xp4[cc] = __shfl_down_sync(0xffffffffu, cen[cc].x, 1); // x[w0+4]
    }
    if (lane == 0) {
#pragma unroll
        for (int cc = 0; cc < C_PER_BLOCK; ++cc) xm1[cc] = cen[cc].x;   // replicate x[0]
    }
    if (lane == 31) {
#pragma unroll
        for (int cc = 0; cc < C_PER_BLOCK; ++cc) xp4[cc] = cen[cc].w;   // replicate x[127]
    }

    // ---- compute + streaming stores ----
#pragma unroll
    for (int cc = 0; cc < C_PER_BLOCK; ++cc) {
        float4 o;
        o.x = cen[cc].x - (eN.x * up[cc].x + eW.x * xm1[cc]   + eE.x * cen[cc].y + eS.x * dn[cc].x);
        o.y = cen[cc].y - (eN.y * up[cc].y + eW.y * cen[cc].x + eE.y * cen[cc].z + eS.y * dn[cc].y);
        o.z = cen[cc].z - (eN.z * up[cc].z + eW.z * cen[cc].y + eE.z * cen[cc].w + eS.z * dn[cc].z);
        o.w = cen[cc].w - (eN.w * up[cc].w + eW.w * cen[cc].z + eE.w * xp4[cc]   + eS.w * dn[cc].w);
        __stcs((float4*)(ob + (long)cc * HW + off_c), o);
    }
}

extern "C" void kernel_launch(void* const* d_in, const int* in_sizes, int n_in,
                              void* d_out, int out_size)
{
    const float* patchs = (const float*)d_in[0];   // [4,8,32,128,128]
    const float* ew     = (const float*)d_in[1];   // [4,8,4,128,128]
    // d_in[2] = node_degree: unused in forward
    float* out = (float*)d_out;                    // [4,8,32,128,128]

    dim3 block(32, ROWS_PER_BLOCK);                           // 256 threads
    dim3 grid(H_DIM / ROWS_PER_BLOCK,                         // 16 h-tiles
              C_DIM / C_PER_BLOCK,                            // 8 c-chunks
              32);                                            // B*G planes

    glrfast_kernel<<<grid, block>>>(patchs, ew, out);
}

// round 15
// speedup vs baseline: 1.0850x; 1.0425x over previous
#include <cuda_runtime.h>
#include <cstdint>

// GLRFast forward: out[b,g,c,h,w] = patchs - sum_e ew[b,g,e,h,w] * nbr_e(patchs)
// nbr order (DELTAS): e0=(-1,0) up, e1=(0,-1) left, e2=(0,1) right, e3=(1,0) down
// Replicate ('edge') padding on H and W borders.
// Shapes: B=4, G=8, C=32, H=128, W=128 (fp32). node_degree (d_in[2]) unused.
//
// R14: cp.async (LDGSTS) 6-deep channel pipeline into SMEM. MLP is decoupled
// from registers: per SM ~160KB of reads in flight vs ~15KB needed to cover
// DRAM latency. Block = 8 h-rows x 128 w for ALL 32 channels of one bg plane;
// 512 blocks = exactly one wave on 148 SMs. ew lives in registers (reused
// x32 channels); w+-1 via warp shuffles; __stcs streaming stores.

#define W_DIM   128
#define H_DIM   128
#define C_DIM   32
#define RPB     8                    // output rows per block
#define IN_ROWS (RPB + 2)            // + replicate halo
#define ROW_PAD 136                  // floats per smem row (128 + 8 pad)
#define DEPTH   6                    // pipeline stages
#define LOADS   (IN_ROWS * 32)       // 320 float4 per stage

#define CP_ASYNC16(smem_u32, gptr) \
    asm volatile("cp.async.cg.shared.global [%0], [%1], 16;\n" :: "r"(smem_u32), "l"(gptr))
#define CP_COMMIT() asm volatile("cp.async.commit_group;\n" ::: "memory")
#define CP_WAIT(n)  asm volatile("cp.async.wait_group %0;\n" :: "n"(n) : "memory")

__device__ __forceinline__ void issue_stage(const float* __restrict__ plane, int c, int h0,
                                            float (*bufc)[ROW_PAD], int tid)
{
    const float* src_c = plane + (long)c * (H_DIM * W_DIM);
#pragma unroll
    for (int i = tid; i < LOADS; i += 256) {
        const int row  = i >> 5;          // 0..9
        const int col4 = i & 31;          // float4 index in row
        int gr = h0 - 1 + row;            // replicate clamp
        gr = gr < 0 ? 0 : (gr > H_DIM - 1 ? H_DIM - 1 : gr);
        const float* g = src_c + (long)gr * W_DIM + col4 * 4;
        uint32_t s = (uint32_t)__cvta_generic_to_shared(&bufc[row][col4 * 4]);
        CP_ASYNC16(s, g);
    }
}

__global__ __launch_bounds__(256) void glrfast_kernel(
    const float* __restrict__ patchs,
    const float* __restrict__ ew,
    float* __restrict__ out)
{
    __shared__ __align__(16) float buf[DEPTH][IN_ROWS][ROW_PAD];   // 32.6 KB

    const int lane = threadIdx.x;                  // 0..31 (one full w-row per warp)
    const int ty   = threadIdx.y;                  // 0..7
    const int tid  = ty * 32 + lane;
    const int h0   = blockIdx.x * RPB;
    const int h    = h0 + ty;
    const int bg   = blockIdx.y;                   // 0..31
    const int w0   = lane * 4;
    const int HW   = H_DIM * W_DIM;

    const float* plane = patchs + (long)bg * C_DIM * HW;
    float*       oplane = out   + (long)bg * C_DIM * HW;
    const long   off_c  = (long)h * W_DIM + w0;

    // Edge weights for this pixel quad (reused across all 32 channels)
    const float* ewb = ew + ((long)bg * 4) * HW + off_c;
    const float4 eN = *(const float4*)(ewb + 0L * HW);
    const float4 eW = *(const float4*)(ewb + 1L * HW);
    const float4 eE = *(const float4*)(ewb + 2L * HW);
    const float4 eS = *(const float4*)(ewb + 3L * HW);

    // ---- prologue: fill the pipeline ----
#pragma unroll
    for (int s = 0; s < DEPTH; ++s) {
        issue_stage(plane, s, h0, buf[s], tid);
        CP_COMMIT();
    }

    // ---- mainloop over channels ----
#pragma unroll 1
    for (int c = 0; c < C_DIM; ++c) {
        const int sb = c % DEPTH;

        CP_WAIT(DEPTH - 1);           // own groups for stage c done
        __syncthreads();              // -> everyone's loads for stage c visible

        const float4 cen = *(const float4*)&buf[sb][ty + 1][w0];
        const float4 up  = *(const float4*)&buf[sb][ty    ][w0];
        const float4 dn  = *(const float4*)&buf[sb][ty + 2][w0];

        // w-direction neighbors via in-warp shuffles (warp == one row)
        float xm1 = __shfl_up_sync(0xffffffffu, cen.w, 1);    // x[w0-1]
        float xp4 = __shfl_down_sync(0xffffffffu, cen.x, 1);  // x[w0+4]
        if (lane == 0)  xm1 = cen.x;                          // replicate x[0]
        if (lane == 31) xp4 = cen.w;                          // replicate x[127]

        float4 o;
        o.x = cen.x - (eN.x * up.x + eW.x * xm1   + eE.x * cen.y + eS.x * dn.x);
        o.y = cen.y - (eN.y * up.y + eW.y * cen.x + eE.y * cen.z + eS.y * dn.y);
        o.z = cen.z - (eN.z * up.z + eW.z * cen.y + eE.z * cen.w + eS.z * dn.z);
        o.w = cen.w - (eN.w * up.w + eW.w * cen.z + eE.w * xp4   + eS.w * dn.w);

        __stcs((float4*)(oplane + (long)c * HW + off_c), o);

        __syncthreads();              // all reads of buf[sb] finished before refill

        const int cn = c + DEPTH;
        if (cn < C_DIM)
            issue_stage(plane, cn, h0, buf[sb], tid);
        CP_COMMIT();                  // commit unconditionally to keep group count aligned
    }
}

extern "C" void kernel_launch(void* const* d_in, const int* in_sizes, int n_in,
                              void* d_out, int out_size)
{
    const float* patchs = (const float*)d_in[0];   // [4,8,32,128,128]
    const float* ew     = (const float*)d_in[1];   // [4,8,4,128,128]
    // d_in[2] = node_degree: unused in forward
    float* out = (float*)d_out;                    // [4,8,32,128,128]

    dim3 block(32, RPB);                           // 256 threads
    dim3 grid(H_DIM / RPB,                         // 16 h-tiles
              32);                                 // B*G planes
    glrfast_kernel<<<grid, block>>>(patchs, ew, out);
}

// round 16
// speedup vs baseline: 1.1019x; 1.0156x over previous
#include <cuda_runtime.h>
#include <cstdint>

// GLRFast forward: out[b,g,c,h,w] = patchs - sum_e ew[b,g,e,h,w] * nbr_e(patchs)
// nbr order (DELTAS): e0=(-1,0) up, e1=(0,-1) left, e2=(0,1) right, e3=(1,0) down
// Replicate ('edge') padding on H and W borders.
// Shapes: B=4, G=8, C=32, H=128, W=128 (fp32). node_degree (d_in[2]) unused.
//
// R15: R14's cp.async channel pipeline, but with the launch geometry fixed:
//  - 8 channels per block -> 2048 blocks (R14's 512 gave only 3.46 blocks/SM
//    of total work: under-occupied + 25% end-of-kernel idle).
//  - ONE __syncthreads per channel (CUTLASS multistage order: the barrier that
//    publishes stage c also proves everyone finished reading stage c-1, whose
//    slot is exactly where stage c+DEPTH-1 is issued).
//  - DEPTH=4, smem 21.8KB; ~5 resident blocks/SM x 3 pending stages x 5.4KB
//    ~= 80KB reads in flight per SM.

#define W_DIM   128
#define H_DIM   128
#define C_DIM   32
#define RPB     8                    // output rows per block
#define C_PB    8                    // channels per block
#define IN_ROWS (RPB + 2)            // + replicate halo
#define ROW_PAD 136                  // floats per smem row (128 + 8 pad)
#define DEPTH   4                    // pipeline stages
#define LOADS   (IN_ROWS * 32)       // 320 float4 per stage

#define CP_ASYNC16(smem_u32, gptr) \
    asm volatile("cp.async.cg.shared.global [%0], [%1], 16;\n" :: "r"(smem_u32), "l"(gptr))
#define CP_COMMIT() asm volatile("cp.async.commit_group;\n" ::: "memory")
#define CP_WAIT(n)  asm volatile("cp.async.wait_group %0;\n" :: "n"(n) : "memory")

__device__ __forceinline__ void issue_stage(const float* __restrict__ cbase, int c, int h0,
                                            float (*bufc)[ROW_PAD], int tid)
{
    const float* src_c = cbase + (long)c * (H_DIM * W_DIM);
#pragma unroll
    for (int i = tid; i < LOADS; i += 256) {
        const int row  = i >> 5;          // 0..9
        const int col4 = i & 31;          // float4 index in row
        int gr = h0 - 1 + row;            // replicate clamp
        gr = gr < 0 ? 0 : (gr > H_DIM - 1 ? H_DIM - 1 : gr);
        const float* g = src_c + (long)gr * W_DIM + col4 * 4;
        uint32_t s = (uint32_t)__cvta_generic_to_shared(&bufc[row][col4 * 4]);
        CP_ASYNC16(s, g);
    }
}

__global__ __launch_bounds__(256) void glrfast_kernel(
    const float* __restrict__ patchs,
    const float* __restrict__ ew,
    float* __restrict__ out)
{
    __shared__ __align__(16) float buf[DEPTH][IN_ROWS][ROW_PAD];   // 21.8 KB

    const int lane = threadIdx.x;                  // 0..31 (one full w-row per warp)
    const int ty   = threadIdx.y;                  // 0..7
    const int tid  = ty * 32 + lane;
    const int h0   = blockIdx.x * RPB;
    const int h    = h0 + ty;
    const int c0   = blockIdx.y * C_PB;
    const int bg   = blockIdx.z;                   // 0..31
    const int w0   = lane * 4;
    const int HW   = H_DIM * W_DIM;

    const float* cbase  = patchs + ((long)bg * C_DIM + c0) * HW;
    float*       obase  = out    + ((long)bg * C_DIM + c0) * HW;
    const long   off_c  = (long)h * W_DIM + w0;

    // Edge weights for this pixel quad (reused across all 8 channels)
    const float* ewb = ew + ((long)bg * 4) * HW + off_c;
    const float4 eN = *(const float4*)(ewb + 0L * HW);
    const float4 eW = *(const float4*)(ewb + 1L * HW);
    const float4 eE = *(const float4*)(ewb + 2L * HW);
    const float4 eS = *(const float4*)(ewb + 3L * HW);

    // ---- prologue: issue stages 0..DEPTH-2 (DEPTH-1 committed groups) ----
#pragma unroll
    for (int s = 0; s < DEPTH - 1; ++s) {
        issue_stage(cbase, s, h0, buf[s], tid);
        CP_COMMIT();
    }

    // ---- mainloop over channels: ONE barrier per channel ----
#pragma unroll 1
    for (int c = 0; c < C_PB; ++c) {
        const int sb = c % DEPTH;

        CP_WAIT(DEPTH - 2);           // stage c's group has landed (this thread)
        __syncthreads();              // stage c visible to all; all done reading c-1

        // issue stage c+DEPTH-1 into slot (c-1)%DEPTH (freed by the barrier above)
        const int cn = c + DEPTH - 1;
        if (cn < C_PB)
            issue_stage(cbase, cn, h0, buf[cn % DEPTH], tid);
        CP_COMMIT();                  // unconditional: keeps group accounting aligned

        // ---- consume stage c ----
        const float4 cen = *(const float4*)&buf[sb][ty + 1][w0];
        const float4 up  = *(const float4*)&buf[sb][ty    ][w0];
        const float4 dn  = *(const float4*)&buf[sb][ty + 2][w0];

        // w-direction neighbors via in-warp shuffles (warp == one row)
        float xm1 = __shfl_up_sync(0xffffffffu, cen.w, 1);    // x[w0-1]
        float xp4 = __shfl_down_sync(0xffffffffu, cen.x, 1);  // x[w0+4]
        if (lane == 0)  xm1 = cen.x;                          // replicate x[0]
        if (lane == 31) xp4 = cen.w;                          // replicate x[127]

        float4 o;
        o.x = cen.x - (eN.x * up.x + eW.x * xm1   + eE.x * cen.y + eS.x * dn.x);
        o.y = cen.y - (eN.y * up.y + eW.y * cen.x + eE.y * cen.z + eS.y * dn.y);
        o.z = cen.z - (eN.z * up.z + eW.z * cen.y + eE.z * cen.w + eS.z * dn.z);
        o.w = cen.w - (eN.w * up.w + eW.w * cen.z + eE.w * xp4   + eS.w * dn.w);

        __stcs((float4*)(obase + (long)c * HW + off_c), o);
    }
}

extern "C" void kernel_launch(void* const* d_in, const int* in_sizes, int n_in,
                              void* d_out, int out_size)
{
    const float* patchs = (const float*)d_in[0];   // [4,8,32,128,128]
    const float* ew     = (const float*)d_in[1];   // [4,8,4,128,128]
    // d_in[2] = node_degree: unused in forward
    float* out = (float*)d_out;                    // [4,8,32,128,128]

    dim3 block(32, RPB);                           // 256 threads
    dim3 grid(H_DIM / RPB,                         // 16 h-tiles
              C_DIM / C_PB,                        // 4 c-chunks
              32);                                 // B*G planes
    glrfast_kernel<<<grid, block>>>(patchs, ew, out);
}

// round 17
// speedup vs baseline: 1.1032x; 1.0012x over previous
#include <cuda_runtime.h>
#include <cstdint>

// GLRFast forward: out[b,g,c,h,w] = patchs - sum_e ew[b,g,e,h,w] * nbr_e(patchs)
// nbr order (DELTAS): e0=(-1,0) up, e1=(0,-1) left, e2=(0,1) right, e3=(1,0) down
// Replicate ('edge') padding on H and W borders.
// Shapes: B=4, G=8, C=32, H=128, W=128 (fp32). node_degree (d_in[2]) unused.
//
// R15: R14's cp.async channel pipeline, but with the launch geometry fixed:
//  - 8 channels per block -> 2048 blocks (R14's 512 gave only 3.46 blocks/SM
//    of total work: under-occupied + 25% end-of-kernel idle).
//  - ONE __syncthreads per channel (CUTLASS multistage order: the barrier that
//    publishes stage c also proves everyone finished reading stage c-1, whose
//    slot is exactly where stage c+DEPTH-1 is issued).
//  - DEPTH=4, smem 21.8KB; ~5 resident blocks/SM x 3 pending stages x 5.4KB
//    ~= 80KB reads in flight per SM.

#define W_DIM   128
#define H_DIM   128
#define C_DIM   32
#define RPB     8                    // output rows per block
#define C_PB    8                    // channels per block
#define IN_ROWS (RPB + 2)            // + replicate halo
#define ROW_PAD 136                  // floats per smem row (128 + 8 pad)
#define DEPTH   4                    // pipeline stages
#define LOADS   (IN_ROWS * 32)       // 320 float4 per stage

#define CP_ASYNC16(smem_u32, gptr) \
    asm volatile("cp.async.cg.shared.global [%0], [%1], 16;\n" :: "r"(smem_u32), "l"(gptr))
#define CP_COMMIT() asm volatile("cp.async.commit_group;\n" ::: "memory")
#define CP_WAIT(n)  asm volatile("cp.async.wait_group %0;\n" :: "n"(n) : "memory")

__device__ __forceinline__ void issue_stage(const float* __restrict__ cbase, int c, int h0,
                                            float (*bufc)[ROW_PAD], int tid)
{
    const float* src_c = cbase + (long)c * (H_DIM * W_DIM);
#pragma unroll
    for (int i = tid; i < LOADS; i += 256) {
        const int row  = i >> 5;          // 0..9
        const int col4 = i & 31;          // float4 index in row
        int gr = h0 - 1 + row;            // replicate clamp
        gr = gr < 0 ? 0 : (gr > H_DIM - 1 ? H_DIM - 1 : gr);
        const float* g = src_c + (long)gr * W_DIM + col4 * 4;
        uint32_t s = (uint32_t)__cvta_generic_to_shared(&bufc[row][col4 * 4]);
        CP_ASYNC16(s, g);
    }
}

__global__ __launch_bounds__(256) void glrfast_kernel(
    const float* __restrict__ patchs,
    const float* __restrict__ ew,
    float* __restrict__ out)
{
    __shared__ __align__(16) float buf[DEPTH][IN_ROWS][ROW_PAD];   // 21.8 KB

    const int lane = threadIdx.x;                  // 0..31 (one full w-row per warp)
    const int ty   = threadIdx.y;                  // 0..7
    const int tid  = ty * 32 + lane;
    const int h0   = blockIdx.x * RPB;
    const int h    = h0 + ty;
    const int c0   = blockIdx.y * C_PB;
    const int bg   = blockIdx.z;                   // 0..31
    const int w0   = lane * 4;
    const int HW   = H_DIM * W_DIM;

    const float* cbase  = patchs + ((long)bg * C_DIM + c0) * HW;
    float*       obase  = out    + ((long)bg * C_DIM + c0) * HW;
    const long   off_c  = (long)h * W_DIM + w0;

    // Edge weights for this pixel quad (reused across all 8 channels)
    const float* ewb = ew + ((long)bg * 4) * HW + off_c;
    const float4 eN = *(const float4*)(ewb + 0L * HW);
    const float4 eW = *(const float4*)(ewb + 1L * HW);
    const float4 eE = *(const float4*)(ewb + 2L * HW);
    const float4 eS = *(const float4*)(ewb + 3L * HW);

    // ---- prologue: issue stages 0..DEPTH-2 (DEPTH-1 committed groups) ----
#pragma unroll
    for (int s = 0; s < DEPTH - 1; ++s) {
        issue_stage(cbase, s, h0, buf[s], tid);
        CP_COMMIT();
    }

    // ---- mainloop over channels: ONE barrier per channel ----
#pragma unroll 1
    for (int c = 0; c < C_PB; ++c) {
        const int sb = c % DEPTH;

        CP_WAIT(DEPTH - 2);           // stage c's group has landed (this thread)
        __syncthreads();              // stage c visible to all; all done reading c-1

        // issue stage c+DEPTH-1 into slot (c-1)%DEPTH (freed by the barrier above)
        const int cn = c + DEPTH - 1;
        if (cn < C_PB)
            issue_stage(cbase, cn, h0, buf[cn % DEPTH], tid);
        CP_COMMIT();                  // unconditional: keeps group accounting aligned

        // ---- consume stage c ----
        const float4 cen = *(const float4*)&buf[sb][ty + 1][w0];
        const float4 up  = *(const float4*)&buf[sb][ty    ][w0];
        const float4 dn  = *(const float4*)&buf[sb][ty + 2][w0];

        // w-direction neighbors via in-warp shuffles (warp == one row)
        float xm1 = __shfl_up_sync(0xffffffffu, cen.w, 1);    // x[w0-1]
        float xp4 = __shfl_down_sync(0xffffffffu, cen.x, 1);  // x[w0+4]
        if (lane == 0)  xm1 = cen.x;                          // replicate x[0]
        if (lane == 31) xp4 = cen.w;                          // replicate x[127]

        float4 o;
        o.x = cen.x - (eN.x * up.x + eW.x * xm1   + eE.x * cen.y + eS.x * dn.x);
        o.y = cen.y - (eN.y * up.y + eW.y * cen.x + eE.y * cen.z + eS.y * dn.y);
        o.z = cen.z - (eN.z * up.z + eW.z * cen.y + eE.z * cen.w + eS.z * dn.z);
        o.w = cen.w - (eN.w * up.w + eW.w * cen.z + eE.w * xp4   + eS.w * dn.w);

        __stcs((float4*)(obase + (long)c * HW + off_c), o);
    }
}

extern "C" void kernel_launch(void* const* d_in, const int* in_sizes, int n_in,
                              void* d_out, int out_size)
{
    const float* patchs = (const float*)d_in[0];   // [4,8,32,128,128]
    const float* ew     = (const float*)d_in[1];   // [4,8,4,128,128]
    // d_in[2] = node_degree: unused in forward
    float* out = (float*)d_out;                    // [4,8,32,128,128]

    dim3 block(32, RPB);                           // 256 threads
    dim3 grid(H_DIM / RPB,                         // 16 h-tiles
              C_DIM / C_PB,                        // 4 c-chunks
              32);                                 // B*G planes
    glrfast_kernel<<<grid, block>>>(patchs, ew, out);
}